// round 17
// baseline (speedup 1.0000x reference)
#include <cuda_runtime.h>
#include <cuda_bf16.h>
#include <cuda_fp16.h>
#include <math.h>
#include <stdint.h>

#define N_MAX 100000
#define E_MAX 1600000
#define D 128
#define WP 136                      // padded pitch (bf16 elems) for mma tiles

// Scratch (static __device__ per allocation rules)
__device__ __half g_bufH1[(size_t)N_MAX * D];        // gemm1 output (x@W1)
__device__ __half g_bufH2[(size_t)N_MAX * D];        // hidden state h1
__device__ __half g_bufH3[(size_t)N_MAX * D];        // gemm2 output (h1@W2)
__device__ float g_t[N_MAX];                         // fused head output
__device__ int   g_cnt[N_MAX];
__device__ int   g_rowptr[N_MAX + 1];
__device__ int   g_cursor[N_MAX];
__device__ __align__(16) int2 g_epack[E_MAX];        // packed (col, val)
__device__ int   g_bsum[256];
// Pre-split weights, transposed Bt[n][k], padded pitch WP (bf16 hi/lo)
__device__ unsigned short g_w_hi[2][128 * WP];
__device__ unsigned short g_w_lo[2][128 * WP];

// ===========================================================================
// Weight prep (side stream, overlapped with CSR build)
// ===========================================================================
__global__ void prep_w_kernel(const float* __restrict__ W1,
                              const float* __restrict__ W2) {
    const float* W = (blockIdx.x == 0) ? W1 : W2;
    unsigned short* hi = g_w_hi[blockIdx.x];
    unsigned short* lo = g_w_lo[blockIdx.x];
    for (int idx = threadIdx.x; idx < 128 * 128; idx += blockDim.x) {
        int k = idx >> 7, nn = idx & 127;
        float w = W[idx];
        __nv_bfloat16 h = __float2bfloat16_rn(w);
        float wl = w - __bfloat162float(h);
        hi[nn * WP + k] = __bfloat16_as_ushort(h);
        lo[nn * WP + k] = __bfloat16_as_ushort(__float2bfloat16_rn(wl));
    }
}

__global__ void zero_int_kernel(int* __restrict__ p, int n) {
    int i = blockIdx.x * blockDim.x + threadIdx.x;
    int stride = gridDim.x * blockDim.x;
    for (; i < n; i += stride) p[i] = 0;
}

// ===========================================================================
// GEMM: C16[rows,128] = fp16( A[rows,128] @ W ), tile range [tile0, tile0+nt)
// ===========================================================================
#define SA_HI 0
#define SA_LO (128 * WP * 2)
#define SB_HI (2 * 128 * WP * 2)
#define SB_LO (3 * 128 * WP * 2)
#define SM_GEMM (4 * 128 * WP * 2)     // 139264 B

__device__ __forceinline__ float2 load2(const float* p) {
    return *reinterpret_cast<const float2*>(p);
}
__device__ __forceinline__ float2 load2(const __half* p) {
    return __half22float2(*reinterpret_cast<const __half2*>(p));
}

#define MMA_BF16(c, a, b) \
    asm volatile( \
        "mma.sync.aligned.m16n8k16.row.col.f32.bf16.bf16.f32 " \
        "{%0,%1,%2,%3}, {%4,%5,%6,%7}, {%8,%9}, {%0,%1,%2,%3};" \
        : "+f"((c)[0]), "+f"((c)[1]), "+f"((c)[2]), "+f"((c)[3]) \
        : "r"((a)[0]), "r"((a)[1]), "r"((a)[2]), "r"((a)[3]), \
          "r"((b)[0]), "r"((b)[1]))

template<typename TIN>
__global__ __launch_bounds__(256) void gemm_mma_kernel(
    const TIN* __restrict__ A, int widx, __half* __restrict__ C16,
    int tile0, int M)
{
    extern __shared__ char smem[];
    const int tid = threadIdx.x;
    const int wid = tid >> 5, lane = tid & 31;
    const int row0 = (tile0 + blockIdx.x) * 128;

    {
        const uint4* whi = reinterpret_cast<const uint4*>(g_w_hi[widx]);
        const uint4* wlo = reinterpret_cast<const uint4*>(g_w_lo[widx]);
        uint4* dh = reinterpret_cast<uint4*>(smem + SB_HI);
        uint4* dl = reinterpret_cast<uint4*>(smem + SB_LO);
        for (int i = tid; i < (128 * WP * 2) / 16; i += 256) {
            dh[i] = whi[i];
            dl[i] = wlo[i];
        }
    }
    {
        unsigned short* sAhi = reinterpret_cast<unsigned short*>(smem + SA_HI);
        unsigned short* sAlo = reinterpret_cast<unsigned short*>(smem + SA_LO);
        for (int idx = tid; idx < 128 * 64; idx += 256) {
            int row = idx >> 6;
            int cp  = (idx & 63) << 1;
            int gr  = row0 + row;
            float2 a = make_float2(0.f, 0.f);
            if (gr < M)
                a = load2(A + (size_t)gr * D + cp);
            __nv_bfloat16 h0 = __float2bfloat16_rn(a.x);
            __nv_bfloat16 h1 = __float2bfloat16_rn(a.y);
            __nv_bfloat16 l0 = __float2bfloat16_rn(a.x - __bfloat162float(h0));
            __nv_bfloat16 l1 = __float2bfloat16_rn(a.y - __bfloat162float(h1));
            int o = row * WP + cp;
            *reinterpret_cast<uint32_t*>(sAhi + o) =
                (uint32_t)__bfloat16_as_ushort(h0) |
                ((uint32_t)__bfloat16_as_ushort(h1) << 16);
            *reinterpret_cast<uint32_t*>(sAlo + o) =
                (uint32_t)__bfloat16_as_ushort(l0) |
                ((uint32_t)__bfloat16_as_ushort(l1) << 16);
        }
    }
    __syncthreads();

    const int wm = (wid & 3) * 32;
    const int wn = (wid >> 2) * 64;
    const int qr = lane >> 2;
    const int qc = (lane & 3) * 2;

    const uint32_t* pAh = reinterpret_cast<const uint32_t*>(smem + SA_HI);
    const uint32_t* pAl = reinterpret_cast<const uint32_t*>(smem + SA_LO);
    const uint32_t* pBh = reinterpret_cast<const uint32_t*>(smem + SB_HI);
    const uint32_t* pBl = reinterpret_cast<const uint32_t*>(smem + SB_LO);
    const int WPW = WP / 2;

    float acc[2][8][4];
    #pragma unroll
    for (int mt = 0; mt < 2; mt++)
        #pragma unroll
        for (int nt = 0; nt < 8; nt++)
            #pragma unroll
            for (int j = 0; j < 4; j++) acc[mt][nt][j] = 0.f;

    #pragma unroll
    for (int ks = 0; ks < 8; ks++) {
        const int kw = (ks * 16 + qc) >> 1;
        uint32_t ah[2][4], al[2][4];
        #pragma unroll
        for (int mt = 0; mt < 2; mt++) {
            int r = wm + mt * 16 + qr;
            int w0 = r * WPW + kw;
            int w1 = (r + 8) * WPW + kw;
            ah[mt][0] = pAh[w0];     ah[mt][1] = pAh[w1];
            ah[mt][2] = pAh[w0 + 4]; ah[mt][3] = pAh[w1 + 4];
            al[mt][0] = pAl[w0];     al[mt][1] = pAl[w1];
            al[mt][2] = pAl[w0 + 4]; al[mt][3] = pAl[w1 + 4];
        }
        uint32_t bh[8][2], bl[8][2];
        #pragma unroll
        for (int nt = 0; nt < 8; nt++) {
            int n = wn + nt * 8 + qr;
            int w0 = n * WPW + kw;
            bh[nt][0] = pBh[w0]; bh[nt][1] = pBh[w0 + 4];
            bl[nt][0] = pBl[w0]; bl[nt][1] = pBl[w0 + 4];
        }
        #pragma unroll
        for (int mt = 0; mt < 2; mt++)
            #pragma unroll
            for (int nt = 0; nt < 8; nt++) {
                MMA_BF16(acc[mt][nt], ah[mt], bh[nt]);
                MMA_BF16(acc[mt][nt], ah[mt], bl[nt]);
                MMA_BF16(acc[mt][nt], al[mt], bh[nt]);
            }
    }

    #pragma unroll
    for (int mt = 0; mt < 2; mt++) {
        int r = row0 + wm + mt * 16 + qr;
        #pragma unroll
        for (int nt = 0; nt < 8; nt++) {
            int col = wn + nt * 8 + qc;
            if (r < M)
                *reinterpret_cast<__half2*>(C16 + (size_t)r * D + col) =
                    __floats2half2_rn(acc[mt][nt][0], acc[mt][nt][1]);
            if (r + 8 < M)
                *reinterpret_cast<__half2*>(C16 + (size_t)(r + 8) * D + col) =
                    __floats2half2_rn(acc[mt][nt][2], acc[mt][nt][3]);
        }
    }
}

// ===========================================================================
// CSR build — vectorized edge streams (int4 = 4 edges per load)
// ===========================================================================
__global__ void hist_kernel(const int* __restrict__ erow, int* __restrict__ cnt, int nE) {
    int gt = blockIdx.x * blockDim.x + threadIdx.x;
    int stride = gridDim.x * blockDim.x;
    int n4 = nE >> 2;
    const int4* er4 = reinterpret_cast<const int4*>(erow);
    for (int i = gt; i < n4; i += stride) {
        int4 e = er4[i];
        atomicAdd(&cnt[e.x], 1);
        atomicAdd(&cnt[e.y], 1);
        atomicAdd(&cnt[e.z], 1);
        atomicAdd(&cnt[e.w], 1);
    }
    int tail = nE & 3;
    if (gt < tail) atomicAdd(&cnt[erow[n4 * 4 + gt]], 1);
}

// Two-level shfl scan: exclusive partials + block sums
__global__ __launch_bounds__(1024) void scan1_kernel(
    const int* __restrict__ cnt, int* __restrict__ excl, int* __restrict__ bsum, int n)
{
    __shared__ int wsum[32];
    int tid = threadIdx.x;
    int lane = tid & 31, wid = tid >> 5;
    int i = blockIdx.x * 1024 + tid;
    int v = (i < n) ? cnt[i] : 0;
    int s = v;
    #pragma unroll
    for (int o = 1; o < 32; o <<= 1) {
        int t = __shfl_up_sync(0xFFFFFFFFu, s, o);
        if (lane >= o) s += t;
    }
    if (lane == 31) wsum[wid] = s;
    __syncthreads();
    if (wid == 0) {
        int w = wsum[lane];
        #pragma unroll
        for (int o = 1; o < 32; o <<= 1) {
            int t = __shfl_up_sync(0xFFFFFFFFu, w, o);
            if (lane >= o) w += t;
        }
        wsum[lane] = w;
    }
    __syncthreads();
    int incl = s + (wid > 0 ? wsum[wid - 1] : 0);
    if (i < n) excl[i] = incl - v;
    if (tid == 1023) bsum[blockIdx.x] = incl;
}

// Combine with inline exclusive scan of bsum (nb <= 128)
__global__ __launch_bounds__(256) void scan3_kernel(
    const int* __restrict__ excl, const int* __restrict__ bsum,
    int* __restrict__ rowptr, int* __restrict__ cursor, int n, int nE, int nb)
{
    __shared__ int sbs[128];
    __shared__ int wpre[4];
    int tid = threadIdx.x;
    int lane = tid & 31, wid = tid >> 5;
    int v = 0, s = 0;
    if (tid < 128) {
        v = (tid < nb) ? bsum[tid] : 0;
        s = v;
        #pragma unroll
        for (int o = 1; o < 32; o <<= 1) {
            int t = __shfl_up_sync(0xFFFFFFFFu, s, o);
            if (lane >= o) s += t;
        }
        if (lane == 31) wpre[wid] = s;
    }
    __syncthreads();
    if (tid < 128) {
        int base = 0;
        #pragma unroll
        for (int k = 0; k < 4; k++)
            if (k < wid) base += wpre[k];
        sbs[tid] = base + s - v;
    }
    __syncthreads();

    int i = blockIdx.x * blockDim.x + tid;
    int stride = gridDim.x * blockDim.x;
    for (; i <= n; i += stride) {
        if (i < n) {
            int rp = excl[i] + sbs[i >> 10];
            rowptr[i] = rp;
            cursor[i] = rp;
        } else {
            rowptr[n] = nE;
        }
    }
}

__global__ void scatter_kernel(
    const int* __restrict__ erow, const int* __restrict__ ecol,
    const float* __restrict__ eval, int* __restrict__ cursor,
    int2* __restrict__ epack, int nE)
{
    int gt = blockIdx.x * blockDim.x + threadIdx.x;
    int stride = gridDim.x * blockDim.x;
    int n4 = nE >> 2;
    const int4* er4 = reinterpret_cast<const int4*>(erow);
    const int4* ec4 = reinterpret_cast<const int4*>(ecol);
    const float4* ev4 = reinterpret_cast<const float4*>(eval);
    for (int i = gt; i < n4; i += stride) {
        int4 r = er4[i];
        int4 c = ec4[i];
        float4 v = ev4[i];
        int p0 = atomicAdd(&cursor[r.x], 1);
        int p1 = atomicAdd(&cursor[r.y], 1);
        int p2 = atomicAdd(&cursor[r.z], 1);
        int p3 = atomicAdd(&cursor[r.w], 1);
        epack[p0] = make_int2(c.x, __float_as_int(v.x));
        epack[p1] = make_int2(c.y, __float_as_int(v.y));
        epack[p2] = make_int2(c.z, __float_as_int(v.z));
        epack[p3] = make_int2(c.w, __float_as_int(v.w));
    }
    int tail = nE & 3;
    if (gt < tail) {
        int i = n4 * 4 + gt;
        int pos = atomicAdd(&cursor[erow[i]], 1);
        epack[pos] = make_int2(ecol[i], __float_as_int(eval[i]));
    }
}

// ===========================================================================
// SpMM core: fp16 gathers, fp32 accumulate. One warp per row, 4 cols/lane.
// ===========================================================================
#define SPMM_FMA(acc, v, g) do { \
    float2 _a01 = __half22float2(*reinterpret_cast<__half2*>(&(g).x)); \
    float2 _a23 = __half22float2(*reinterpret_cast<__half2*>(&(g).y)); \
    (acc).x = fmaf((v), _a01.x, (acc).x); (acc).y = fmaf((v), _a01.y, (acc).y); \
    (acc).z = fmaf((v), _a23.x, (acc).z); (acc).w = fmaf((v), _a23.y, (acc).w); \
} while (0)

__device__ __forceinline__ float4 spmm_row_acc(
    const int2* __restrict__ epack, const __half* __restrict__ X,
    int beg, int end, int lane)
{
    float4 acc = make_float4(0.f, 0.f, 0.f, 0.f);
    int i = beg;
    if ((i & 1) && i < end) {
        int2 e = epack[i];
        uint2 g = *reinterpret_cast<const uint2*>(X + (size_t)e.x * D + lane * 4);
        SPMM_FMA(acc, __int_as_float(e.y), g);
        i++;
    }
    for (; i + 8 <= end; i += 8) {
        int4 ep0 = *reinterpret_cast<const int4*>(epack + i);
        int4 ep1 = *reinterpret_cast<const int4*>(epack + i + 2);
        int4 ep2 = *reinterpret_cast<const int4*>(epack + i + 4);
        int4 ep3 = *reinterpret_cast<const int4*>(epack + i + 6);
        uint2 g[8];
        g[0] = *reinterpret_cast<const uint2*>(X + (size_t)ep0.x * D + lane * 4);
        g[1] = *reinterpret_cast<const uint2*>(X + (size_t)ep0.z * D + lane * 4);
        g[2] = *reinterpret_cast<const uint2*>(X + (size_t)ep1.x * D + lane * 4);
        g[3] = *reinterpret_cast<const uint2*>(X + (size_t)ep1.z * D + lane * 4);
        g[4] = *reinterpret_cast<const uint2*>(X + (size_t)ep2.x * D + lane * 4);
        g[5] = *reinterpret_cast<const uint2*>(X + (size_t)ep2.z * D + lane * 4);
        g[6] = *reinterpret_cast<const uint2*>(X + (size_t)ep3.x * D + lane * 4);
        g[7] = *reinterpret_cast<const uint2*>(X + (size_t)ep3.z * D + lane * 4);
        SPMM_FMA(acc, __int_as_float(ep0.y), g[0]);
        SPMM_FMA(acc, __int_as_float(ep0.w), g[1]);
        SPMM_FMA(acc, __int_as_float(ep1.y), g[2]);
        SPMM_FMA(acc, __int_as_float(ep1.w), g[3]);
        SPMM_FMA(acc, __int_as_float(ep2.y), g[4]);
        SPMM_FMA(acc, __int_as_float(ep2.w), g[5]);
        SPMM_FMA(acc, __int_as_float(ep3.y), g[6]);
        SPMM_FMA(acc, __int_as_float(ep3.w), g[7]);
    }
    for (; i + 2 <= end; i += 2) {
        int4 ep = *reinterpret_cast<const int4*>(epack + i);
        uint2 g0 = *reinterpret_cast<const uint2*>(X + (size_t)ep.x * D + lane * 4);
        uint2 g1 = *reinterpret_cast<const uint2*>(X + (size_t)ep.z * D + lane * 4);
        SPMM_FMA(acc, __int_as_float(ep.y), g0);
        SPMM_FMA(acc, __int_as_float(ep.w), g1);
    }
    if (i < end) {
        int2 e = epack[i];
        uint2 g = *reinterpret_cast<const uint2*>(X + (size_t)e.x * D + lane * 4);
        SPMM_FMA(acc, __int_as_float(e.y), g);
    }
    return acc;
}

// Layer-1 SpMM over row range [rbase, rbase+rcount): out = fp16(relu(A@X + b))
__global__ __launch_bounds__(256) void spmm_csr_h_bias_relu_kernel(
    const int* __restrict__ rowptr, const int2* __restrict__ epack,
    const __half* __restrict__ X,
    const float* __restrict__ bias, __half* __restrict__ out,
    int rbase, int rcount)
{
    int gt = blockIdx.x * blockDim.x + threadIdx.x;
    int rr = gt >> 5;
    int lane = gt & 31;
    if (rr >= rcount) return;
    int r = rbase + rr;

    float4 acc = spmm_row_acc(epack, X, rowptr[r], rowptr[r + 1], lane);

    const float4 b = *reinterpret_cast<const float4*>(bias + lane * 4);
    __half2 o01 = __floats2half2_rn(fmaxf(acc.x + b.x, 0.f), fmaxf(acc.y + b.y, 0.f));
    __half2 o23 = __floats2half2_rn(fmaxf(acc.z + b.z, 0.f), fmaxf(acc.w + b.w, 0.f));
    uint2 ov;
    ov.x = *reinterpret_cast<uint32_t*>(&o01);
    ov.y = *reinterpret_cast<uint32_t*>(&o23);
    *reinterpret_cast<uint2*>(out + (size_t)r * D + lane * 4) = ov;
}

// Layer-2 SpMM with fused head GEMV: t[r] = dot(relu(A@X + bias), Wout)
__global__ __launch_bounds__(256) void spmm_csr_relu_gemv_kernel(
    const int* __restrict__ rowptr, const int2* __restrict__ epack,
    const __half* __restrict__ X,
    const float* __restrict__ bias, const float* __restrict__ Wout,
    float* __restrict__ t, int M)
{
    int gt = blockIdx.x * blockDim.x + threadIdx.x;
    int r = gt >> 5;
    int lane = gt & 31;
    if (r >= M) return;

    float4 acc = spmm_row_acc(epack, X, rowptr[r], rowptr[r + 1], lane);

    const float4 b = *reinterpret_cast<const float4*>(bias + lane * 4);
    const float4 w = *reinterpret_cast<const float4*>(Wout + lane * 4);
    float s = fmaxf(acc.x + b.x, 0.f) * w.x
            + fmaxf(acc.y + b.y, 0.f) * w.y
            + fmaxf(acc.z + b.z, 0.f) * w.z
            + fmaxf(acc.w + b.w, 0.f) * w.w;
    #pragma unroll
    for (int o = 16; o > 0; o >>= 1)
        s += __shfl_xor_sync(0xFFFFFFFFu, s, o);
    if (lane == 0) t[r] = s;
}

// ---------------------------------------------------------------------------
// Scalar CSR SpMM + softplus
// ---------------------------------------------------------------------------
__global__ __launch_bounds__(256) void spmm_csr_scalar_softplus_kernel(
    const int* __restrict__ rowptr, const int2* __restrict__ epack,
    const float* __restrict__ t,
    const float* __restrict__ bout, float* __restrict__ out, int M)
{
    int r = blockIdx.x * blockDim.x + threadIdx.x;
    if (r >= M) return;
    int beg = rowptr[r], end = rowptr[r + 1];
    float acc = 0.f;
    for (int i = beg; i < end; i++) {
        int2 e = epack[i];
        acc = fmaf(__int_as_float(e.y), t[e.x], acc);
    }
    float s = acc + bout[0];
    out[r] = fmaxf(s, 0.f) + log1pf(expf(-fabsf(s)));
}

// ===========================================================================
// Launch — fork/join pipeline:
//   side: prep_w -> gemm1            (hidden under CSR build)
//   main: CSR build -> spmm1_c0 -> spmm1_c1
//   side: gemm2_c0 (after spmm1_c0, overlaps spmm1_c1) -> gemm2_c1
//   main: spmm2 -> softplus
// ===========================================================================
extern "C" void kernel_launch(void* const* d_in, const int* in_sizes, int n_in,
                              void* d_out, int out_size)
{
    const float* x     = (const float*)d_in[0];
    const int*   erow  = (const int*)  d_in[1];
    const int*   ecol  = (const int*)  d_in[2];
    const float* eval  = (const float*)d_in[3];
    const float* W1    = (const float*)d_in[4];
    const float* b1    = (const float*)d_in[5];
    const float* W2    = (const float*)d_in[6];
    const float* b2    = (const float*)d_in[7];
    const float* Wout  = (const float*)d_in[8];
    const float* bout  = (const float*)d_in[9];
    float* out = (float*)d_out;

    const int M  = in_sizes[0] / D;     // 100000
    const int nE = in_sizes[1];         // 1600000

    float *tvec;
    __half *bufH1, *bufH2, *bufH3;
    int *cnt, *rowptr, *cursor, *bsum;
    int2* epack;
    cudaGetSymbolAddress((void**)&bufH1,  g_bufH1);
    cudaGetSymbolAddress((void**)&bufH2,  g_bufH2);
    cudaGetSymbolAddress((void**)&bufH3,  g_bufH3);
    cudaGetSymbolAddress((void**)&tvec,   g_t);
    cudaGetSymbolAddress((void**)&cnt,    g_cnt);
    cudaGetSymbolAddress((void**)&rowptr, g_rowptr);
    cudaGetSymbolAddress((void**)&cursor, g_cursor);
    cudaGetSymbolAddress((void**)&epack,  g_epack);
    cudaGetSymbolAddress((void**)&bsum,   g_bsum);

    cudaFuncSetAttribute(gemm_mma_kernel<float>,
                         cudaFuncAttributeMaxDynamicSharedMemorySize, SM_GEMM);
    cudaFuncSetAttribute(gemm_mma_kernel<__half>,
                         cudaFuncAttributeMaxDynamicSharedMemorySize, SM_GEMM);

    const int nb = (M + 1023) / 1024;                // 98
    const int tileBlocks = (M + 127) / 128;          // 782
    const int rowBlocks  = (M + 255) / 256;

    // Chunk split at tile boundary
    const int splitTiles = tileBlocks / 2;           // 391
    const int splitRows  = splitTiles * 128;         // 50048
    const int rows0 = splitRows, rows1 = M - splitRows;
    const int spmmB0 = (rows0 * 32 + 255) / 256;
    const int spmmB1 = (rows1 * 32 + 255) / 256;
    const int spmmBlocks = (M * 32 + 255) / 256;

    cudaStream_t ms = cudaStreamPerThread;
    cudaStream_t side;
    cudaStreamCreateWithFlags(&side, cudaStreamNonBlocking);
    cudaEvent_t evFork, evG1, evS0, evJoin;
    cudaEventCreateWithFlags(&evFork, cudaEventDisableTiming);
    cudaEventCreateWithFlags(&evG1,   cudaEventDisableTiming);
    cudaEventCreateWithFlags(&evS0,   cudaEventDisableTiming);
    cudaEventCreateWithFlags(&evJoin, cudaEventDisableTiming);

    // Fork: side stream runs weight prep + gemm1 (independent of CSR build)
    cudaEventRecord(evFork, ms);
    cudaStreamWaitEvent(side, evFork, 0);
    prep_w_kernel<<<2, 256, 0, side>>>(W1, W2);
    gemm_mma_kernel<float><<<tileBlocks, 256, SM_GEMM, side>>>(x, 0, bufH1, 0, M);
    cudaEventRecord(evG1, side);

    // Main stream: CSR build
    zero_int_kernel<<<128, 256, 0, ms>>>(cnt, M);
    hist_kernel<<<1024, 256, 0, ms>>>(erow, cnt, nE);
    scan1_kernel<<<nb, 1024, 0, ms>>>(cnt, cnt, bsum, M);
    scan3_kernel<<<256, 256, 0, ms>>>(cnt, bsum, rowptr, cursor, M, nE, nb);
    scatter_kernel<<<1024, 256, 0, ms>>>(erow, ecol, eval, cursor, epack, nE);

    // spmm1 needs CSR + gemm1
    cudaStreamWaitEvent(ms, evG1, 0);

    // spmm1 chunk 0 -> evS0; chunk 1 continues on main
    spmm_csr_h_bias_relu_kernel<<<spmmB0, 256, 0, ms>>>(
        rowptr, epack, bufH1, b1, bufH2, 0, rows0);
    cudaEventRecord(evS0, ms);
    spmm_csr_h_bias_relu_kernel<<<spmmB1, 256, 0, ms>>>(
        rowptr, epack, bufH1, b1, bufH2, splitRows, rows1);

    // side: gemm2 chunk 0 overlaps spmm1 chunk 1 (output to bufH3, no race)
    cudaStreamWaitEvent(side, evS0, 0);
    gemm_mma_kernel<__half><<<splitTiles, 256, SM_GEMM, side>>>(
        bufH2, 1, bufH3, 0, M);

    // main: gemm2 chunk 1 (needs spmm1 chunk 1, already ordered on main)
    gemm_mma_kernel<__half><<<tileBlocks - splitTiles, 256, SM_GEMM, ms>>>(
        bufH2, 1, bufH3, splitTiles, M);

    // join: spmm2 needs both gemm2 chunks
    cudaEventRecord(evJoin, side);
    cudaStreamWaitEvent(ms, evJoin, 0);

    // Layer 2 + head GEMV fused: t = relu(A @ gemm2out + b2) . Wout
    spmm_csr_relu_gemv_kernel<<<spmmBlocks, 256, 0, ms>>>(
        rowptr, epack, bufH3, b2, Wout, tvec, M);

    // out = softplus(A @ t + bout)
    spmm_csr_scalar_softplus_kernel<<<rowBlocks, 256, 0, ms>>>(
        rowptr, epack, tvec, bout, out, M);

    cudaEventDestroy(evFork);
    cudaEventDestroy(evG1);
    cudaEventDestroy(evS0);
    cudaEventDestroy(evJoin);
    cudaStreamDestroy(side);
}